// round 16
// baseline (speedup 1.0000x reference)
#include <cuda_runtime.h>
#include <math.h>

#define S      4096
#define E      512
#define H      8
#define DH     64
#define NB     64
#define NH     4
#define FLAT   (NH*S)        // 16384
#define NCHUNK (NH*NB)       // 256
#define BH     H             // batch=1
#define FF     (4*E)         // 2048
#define NVOCAB 32000

// ---------------- scratch (device globals; no allocations allowed) ----------
__device__ float g_x1[S*E];
__device__ float g_x2[S*E];
__device__ float g_xn[S*E];
__device__ float g_qk[S*E];      // [s][h*64+d]
__device__ float g_v [S*E];
__device__ float g_attn[S*E];
__device__ float g_sum[S*E];
__device__ float g_ffh[S*FF];
__device__ int   g_buckets[BH*FLAT];
__device__ int   g_sidx[BH*FLAT];
__device__ float g_o[BH*NH*S*DH];
__device__ float g_logit[BH*NH*S];

// ================= XLA-CPU (strict-FP, scalar libm) arithmetic ===============
// exp/log: correctly-rounded f32 via fp64 (== glibc scalar expf/logf).
__device__ __forceinline__ float exp_cr(float x) {
    return (float)exp((double)x);
}
__device__ __forceinline__ float log_cr(float x) {
    return (float)log((double)x);
}

// lax.rsqrt on CPU: 1.0/sqrt(x), both correctly rounded.
__device__ __forceinline__ float rsqrt_cr(float x) {
    return __fdiv_rn(1.0f, __fsqrt_rn(x));
}

// XLA EmitTanh f32 rational approximation (exact coefficients).
__device__ __forceinline__ float tanh_xla(float x) {
    float ax = fabsf(x);
    if (ax < 0.0004f) return x;
    float xc = fminf(fmaxf(x, -7.90531110763549805f), 7.90531110763549805f);
    float x2 = __fmul_rn(xc, xc);
    float p = -2.76076847742355e-16f;
    p = fmaf(p, x2, 2.00018790482477e-13f);
    p = fmaf(p, x2, -8.60467152213735e-11f);
    p = fmaf(p, x2, 5.12229709037114e-08f);
    p = fmaf(p, x2, 1.48572235717979e-05f);
    p = fmaf(p, x2, 6.37261928875436e-04f);
    p = fmaf(p, x2, 4.89352455891786e-03f);
    float num = __fmul_rn(xc, p);
    float q = 1.19825839466702e-06f;
    q = fmaf(q, x2, 1.18534705686654e-04f);
    q = fmaf(q, x2, 2.26843463243900e-03f);
    q = fmaf(q, x2, 4.89352518554385e-03f);
    return __fdiv_rn(num, q);
}

// jax.nn.gelu approximate=True with Python left-assoc: (0.5*x)*(1+tanh(u)),
// u = c*(x + 0.044715*x^3), x^3=(x*x)*x. Unfused (strict-FP reference).
__device__ __forceinline__ float gelu_xla(float x) {
    float x2 = __fmul_rn(x, x);
    float x3 = __fmul_rn(x2, x);
    float inner = __fadd_rn(x, __fmul_rn(0.044715f, x3));
    float u = __fmul_rn(0.7978845608028654f, inner);
    float t = tanh_xla(u);
    float halfx = __fmul_rn(0.5f, x);
    return __fmul_rn(halfx, __fadd_rn(1.0f, t));
}

// ---------------- embed -----------------------------------------------------
__global__ void embed_kernel(const int* __restrict__ tokens,
                             const float* __restrict__ tok_emb,
                             const float* __restrict__ pos_emb) {
    int i = blockIdx.x * blockDim.x + threadIdx.x;
    if (i < S*E) {
        int s = i / E, e = i % E;
        float val = __fadd_rn(tok_emb[tokens[s]*E + e], pos_emb[i]);
        g_x1[i] = val; g_x2[i] = val;
    }
}

// ---------------- layernorm: one thread per row, STRICT SEQUENTIAL reduces ---
__global__ void ln_kernel(const float* __restrict__ x,
                          const float* __restrict__ g,
                          const float* __restrict__ b,
                          float* __restrict__ y) {
    int row = blockIdx.x * blockDim.x + threadIdx.x;
    if (row >= S) return;
    const float* xr = x + (long)row*E;
    float s = 0.f;
    for (int e = 0; e < E; e++) s = __fadd_rn(s, xr[e]);
    float mean = __fdiv_rn(s, 512.0f);
    float vs = 0.f;
    for (int e = 0; e < E; e++) {
        float d = __fsub_rn(xr[e], mean);
        vs = __fadd_rn(vs, __fmul_rn(d, d));
    }
    float var = __fdiv_rn(vs, 512.0f);
    float rstd = rsqrt_cr(__fadd_rn(var, 1e-3f));
    for (int e = 0; e < E; e++) {
        float d = __fsub_rn(xr[e], mean);
        y[(long)row*E + e] = __fadd_rn(__fmul_rn(__fmul_rn(d, rstd), g[e]), b[e]);
    }
}

// ---------------- tiled GEMM: sequential-k FMA == Eigen gebp chain -----------
// Large canonical 2D matmuls -> Eigen runtime (FMA, sequential ascending k).
// C[M,N] = act(A@B + bias) + resid  (act: 0 none, 1 gelu). Epilogue unfused.
__global__ void gemm_kernel(const float* __restrict__ A, const float* __restrict__ B,
                            const float* __restrict__ bias, const float* __restrict__ resid,
                            float* __restrict__ C, int M, int N, int K, int act) {
    __shared__ float As[16][65];
    __shared__ float Bs[16][64];
    int t  = threadIdx.x;           // 256
    int tx = t & 15, ty = t >> 4;
    int m0 = blockIdx.y * 64, n0 = blockIdx.x * 64;
    float acc[4][4] = {};
    for (int k0 = 0; k0 < K; k0 += 16) {
        for (int l = t; l < 1024; l += 256) {
            int mi = l >> 4, ki = l & 15;
            As[ki][mi] = A[(m0+mi)*K + k0+ki];
            int ki2 = l >> 6, ni = l & 63;
            Bs[ki2][ni] = B[(k0+ki2)*N + n0+ni];
        }
        __syncthreads();
        #pragma unroll
        for (int kk = 0; kk < 16; kk++) {   // ascending k overall
            float a[4], b[4];
            #pragma unroll
            for (int i = 0; i < 4; i++) a[i] = As[kk][ty*4+i];
            #pragma unroll
            for (int j = 0; j < 4; j++) b[j] = Bs[kk][tx*4+j];
            #pragma unroll
            for (int i = 0; i < 4; i++)
                #pragma unroll
                for (int j = 0; j < 4; j++)
                    acc[i][j] = fmaf(a[i], b[j], acc[i][j]);
        }
        __syncthreads();
    }
    #pragma unroll
    for (int i = 0; i < 4; i++) {
        int row = m0 + ty*4 + i;
        #pragma unroll
        for (int j = 0; j < 4; j++) {
            int col = n0 + tx*4 + j;
            float v = acc[i][j];
            if (bias)  v = __fadd_rn(v, bias[col]);
            if (act)   v = gelu_xla(v);
            if (resid) v = __fadd_rn(resid[(long)row*N + col], v);
            C[(long)row*N + col] = v;
        }
    }
}

// ---------------- LSH bucketing: large 2D einsum -> Eigen FMA sequential -----
__global__ void bucket_kernel(const float* __restrict__ rot) {
    int s = blockIdx.x, h = blockIdx.y, t = threadIdx.x;
    __shared__ float q[64];
    if (t < 64) q[t] = g_qk[s*E + h*DH + t];
    __syncthreads();
    int hash = t >> 5, r = t & 31;
    float v = 0.f;
    #pragma unroll 8
    for (int dd = 0; dd < 64; dd++)
        v = fmaf(q[dd], rot[dd*(NH*32) + hash*32 + r], v);
    float val; int idx;
    if (v >= -v) { val = v;  idx = r; }
    else         { val = -v; idx = r + 32; }
    unsigned mask = 0xffffffffu;
    for (int off = 16; off; off >>= 1) {
        float ov = __shfl_down_sync(mask, val, off);
        int   oi = __shfl_down_sync(mask, idx, off);
        if (ov > val || (ov == val && oi < idx)) { val = ov; idx = oi; }
    }
    if (r == 0) g_buckets[h*FLAT + hash*S + s] = idx + hash*NB;
}

// ---------------- stable counting sort (per bh; 256 bins) --------------------
__global__ void sort_kernel() {
    int bh = blockIdx.x, t = threadIdx.x;    // 256 threads
    const int* bk = g_buckets + bh*FLAT;
    int cnt = 0;
    #pragma unroll 8
    for (int i = 0; i < FLAT; i++) cnt += (bk[i] == t);
    __shared__ int c[256];
    c[t] = cnt; __syncthreads();
    int off = 0;
    for (int j = 0; j < t; j++) off += c[j];
    int* dst = g_sidx + bh*FLAT;
    #pragma unroll 4
    for (int i = 0; i < FLAT; i++)
        if (bk[i] == t) dst[off++] = i;
}

// ---------------- chunked attention ------------------------------------------
// BATCHED small einsums (dots, probs@bv): XLA-CPU emits strict LLVM loops ->
// mul and add SEPARATELY ROUNDED (no FMA contraction). This round's knob.
#define SK_LD   65
#define DOTS_LD 129
#define ATTN_SMEM_BYTES ((128*SK_LD*3 + 64*DOTS_LD + 128)*4 + 256*4)

__global__ void attn_kernel() {
    extern __shared__ float sh[];
    float* sk    = sh;                       // [128][65] raw qk rows
    float* bvs   = sk  + 128*SK_LD;          // [128][65] v rows
    float* bkn   = bvs + 128*SK_LD;          // [128][65] normalized keys (f32)
    float* dots  = bkn + 128*SK_LD;          // [64][129]
    float* rnorm = dots + 64*DOTS_LD;        // [128]
    int*   spos  = (int*)(rnorm + 128);      // [128]
    int*   shash = spos + 128;               // [128]

    int c  = blockIdx.x;
    int bh = blockIdx.y;
    int t  = threadIdx.x;
    int cp = (c + NCHUNK - 1) % NCHUNK;

    if (t < 128) {
        int kr = t;
        int js = (kr < 64) ? (c*64 + kr) : (cp*64 + (kr - 64));
        int i  = g_sidx[bh*FLAT + js];
        spos[kr]  = i & (S-1);
        shash[kr] = i >> 12;
    }
    __syncthreads();

    for (int idx = t; idx < 128*64; idx += 256) {
        int kr = idx >> 6, dd = idx & 63;
        int p = spos[kr];
        sk [kr*SK_LD + dd] = g_qk[p*E + bh*DH + dd];
        bvs[kr*SK_LD + dd] = g_v [p*E + bh*DH + dd];
    }
    __syncthreads();

    // sum of squares: strict sequential, unfused mul/add
    if (t < 128) {
        float ss = 0.f;
        for (int dd = 0; dd < 64; dd++) {
            float v = sk[t*SK_LD+dd];
            ss = __fadd_rn(ss, __fmul_rn(v, v));
        }
        rnorm[t] = rsqrt_cr(__fadd_rn(ss, 1e-12f));
    }
    __syncthreads();

    for (int idx = t; idx < 128*64; idx += 256) {
        int kr = idx >> 6, dd = idx & 63;
        bkn[kr*SK_LD + dd] = __fmul_rn(sk[kr*SK_LD + dd], rnorm[kr]);
    }
    __syncthreads();

    // dots = (bq . bkn) [UNFUSED mul+add, sequential] * 0.125, self-pos mask
    // (0.125 multiply is exact — power of two)
    for (int task = t; task < 64*32; task += 256) {
        int r = task >> 5, k0 = (task & 31) * 4;
        float a0=0.f, a1=0.f, a2=0.f, a3=0.f;
        #pragma unroll 8
        for (int dd = 0; dd < 64; dd++) {
            float q = sk[r*SK_LD + dd];
            a0 = __fadd_rn(a0, __fmul_rn(q, bkn[(k0+0)*SK_LD+dd]));
            a1 = __fadd_rn(a1, __fmul_rn(q, bkn[(k0+1)*SK_LD+dd]));
            a2 = __fadd_rn(a2, __fmul_rn(q, bkn[(k0+2)*SK_LD+dd]));
            a3 = __fadd_rn(a3, __fmul_rn(q, bkn[(k0+3)*SK_LD+dd]));
        }
        int pr = spos[r];
        dots[r*DOTS_LD+k0+0] = (pr == spos[k0+0]) ? -5e4f : __fmul_rn(a0, 0.125f);
        dots[r*DOTS_LD+k0+1] = (pr == spos[k0+1]) ? -5e4f : __fmul_rn(a1, 0.125f);
        dots[r*DOTS_LD+k0+2] = (pr == spos[k0+2]) ? -5e4f : __fmul_rn(a2, 0.125f);
        dots[r*DOTS_LD+k0+3] = (pr == spos[k0+3]) ? -5e4f : __fmul_rn(a3, 0.125f);
    }
    __syncthreads();

    // logsumexp (strict sequential sum, correctly-rounded exp/log)
    if (t < 64) {
        float m = -1e30f;
        for (int k = 0; k < 128; k++) m = fmaxf(m, dots[t*DOTS_LD+k]);
        float ssum = 0.f;
        for (int k = 0; k < 128; k++)
            ssum = __fadd_rn(ssum, exp_cr(__fsub_rn(dots[t*DOTS_LD+k], m)));
        float lse = __fadd_rn(log_cr(ssum), m);
        g_logit[(bh*NH + shash[t])*S + spos[t]] = lse;
        for (int k = 0; k < 128; k++)
            dots[t*DOTS_LD+k] = exp_cr(__fsub_rn(dots[t*DOTS_LD+k], lse));
    }
    __syncthreads();

    // bo = probs @ bv (UNFUSED mul+add, sequential over k), scatter-unsort
    for (int task = t; task < 64*16; task += 256) {
        int r = task >> 4, d0 = (task & 15) * 4;
        float o0=0.f, o1=0.f, o2=0.f, o3=0.f;
        for (int k = 0; k < 128; k++) {
            float p = dots[r*DOTS_LD + k];
            o0 = __fadd_rn(o0, __fmul_rn(p, bvs[k*SK_LD + d0+0]));
            o1 = __fadd_rn(o1, __fmul_rn(p, bvs[k*SK_LD + d0+1]));
            o2 = __fadd_rn(o2, __fmul_rn(p, bvs[k*SK_LD + d0+2]));
            o3 = __fadd_rn(o3, __fmul_rn(p, bvs[k*SK_LD + d0+3]));
        }
        long base = ((long)(bh*NH + shash[r])*S + spos[r])*DH + d0;
        g_o[base+0] = o0; g_o[base+1] = o1; g_o[base+2] = o2; g_o[base+3] = o3;
    }
}

// ---------------- combine hash rounds (strict sequential, cr exp/log) --------
__global__ void combine_kernel() {
    int gid = blockIdx.x * blockDim.x + threadIdx.x;
    if (gid >= BH*S*DH) return;
    int dd  = gid & 63;
    int pos = (gid >> 6) & (S-1);
    int bh  = gid >> 18;
    float l0 = g_logit[(bh*NH+0)*S+pos];
    float l1 = g_logit[(bh*NH+1)*S+pos];
    float l2 = g_logit[(bh*NH+2)*S+pos];
    float l3 = g_logit[(bh*NH+3)*S+pos];
    float m  = fmaxf(fmaxf(fmaxf(l0,l1),l2),l3);
    float s4 = 0.f;
    s4 = __fadd_rn(s4, exp_cr(__fsub_rn(l0,m)));
    s4 = __fadd_rn(s4, exp_cr(__fsub_rn(l1,m)));
    s4 = __fadd_rn(s4, exp_cr(__fsub_rn(l2,m)));
    s4 = __fadd_rn(s4, exp_cr(__fsub_rn(l3,m)));
    float lse4 = __fadd_rn(log_cr(s4), m);
    float w0 = exp_cr(__fsub_rn(l0,lse4)), w1 = exp_cr(__fsub_rn(l1,lse4));
    float w2 = exp_cr(__fsub_rn(l2,lse4)), w3 = exp_cr(__fsub_rn(l3,lse4));
    float acc = 0.f;
    acc = __fadd_rn(acc, __fmul_rn(g_o[((long)(bh*NH+0)*S+pos)*DH+dd], w0));
    acc = __fadd_rn(acc, __fmul_rn(g_o[((long)(bh*NH+1)*S+pos)*DH+dd], w1));
    acc = __fadd_rn(acc, __fmul_rn(g_o[((long)(bh*NH+2)*S+pos)*DH+dd], w2));
    acc = __fadd_rn(acc, __fmul_rn(g_o[((long)(bh*NH+3)*S+pos)*DH+dd], w3));
    g_attn[pos*E + bh*DH + dd] = acc;
}

// ---------------- x1 + x2 -----------------------------------------------------
__global__ void sum_kernel() {
    int i = blockIdx.x * blockDim.x + threadIdx.x;
    if (i < S*E) g_sum[i] = __fadd_rn(g_x1[i], g_x2[i]);
}

// ---------------- launch -------------------------------------------------------
extern "C" void kernel_launch(void* const* d_in, const int* in_sizes, int n_in,
                              void* d_out, int out_size) {
    const int*   tokens  = (const int*)  d_in[0];
    const float* tok_emb = (const float*)d_in[1];
    const float* pos_emb = (const float*)d_in[2];
    const float* ln_f_g  = (const float*)d_in[3];
    const float* ln_f_b  = (const float*)d_in[4];
    const float* Wqk     = (const float*)d_in[5];
    const float* Wv      = (const float*)d_in[6];
    const float* Wo      = (const float*)d_in[7];
    const float* bo      = (const float*)d_in[8];
    const float* ln_g_g  = (const float*)d_in[9];
    const float* ln_g_b  = (const float*)d_in[10];
    const float* W1      = (const float*)d_in[11];
    const float* b1      = (const float*)d_in[12];
    const float* W2      = (const float*)d_in[13];
    const float* b2      = (const float*)d_in[14];
    const float* rot     = (const float*)d_in[15];
    const float* Wl      = (const float*)d_in[16];
    const float* bl      = (const float*)d_in[17];
    float* out = (float*)d_out;

    cudaFuncSetAttribute(attn_kernel, cudaFuncAttributeMaxDynamicSharedMemorySize,
                         ATTN_SMEM_BYTES);

    float *px1, *px2, *pxn, *pqk, *pv, *pattn, *pffh, *psum;
    cudaGetSymbolAddress((void**)&px1,  g_x1);
    cudaGetSymbolAddress((void**)&px2,  g_x2);
    cudaGetSymbolAddress((void**)&pxn,  g_xn);
    cudaGetSymbolAddress((void**)&pqk,  g_qk);
    cudaGetSymbolAddress((void**)&pv,   g_v);
    cudaGetSymbolAddress((void**)&pattn,g_attn);
    cudaGetSymbolAddress((void**)&pffh, g_ffh);
    cudaGetSymbolAddress((void**)&psum, g_sum);

    embed_kernel<<<(S*E+255)/256, 256>>>(tokens, tok_emb, pos_emb);

    for (int d = 0; d < 4; d++) {
        // attention branch: y1 = x1 + attn(LN(x2))
        ln_kernel<<<S/128, 128>>>(px2, ln_f_g + d*E, ln_f_b + d*E, pxn);
        gemm_kernel<<<dim3(E/64, S/64), 256>>>(pxn, Wqk + (long)d*E*E, nullptr, nullptr,
                                               pqk, S, E, E, 0);
        gemm_kernel<<<dim3(E/64, S/64), 256>>>(pxn, Wv  + (long)d*E*E, nullptr, nullptr,
                                               pv,  S, E, E, 0);
        bucket_kernel<<<dim3(S, H), 128>>>(rot + (long)d*DH*NH*32);
        sort_kernel<<<BH, 256>>>();
        attn_kernel<<<dim3(NCHUNK, BH), 256, ATTN_SMEM_BYTES>>>();
        combine_kernel<<<(BH*S*DH + 255)/256, 256>>>();
        gemm_kernel<<<dim3(E/64, S/64), 256>>>(pattn, Wo + (long)d*E*E, bo + d*E, px1,
                                               px1, S, E, E, 0);
        // ffn branch: y2 = x2 + FFN(LN(y1))
        ln_kernel<<<S/128, 128>>>(px1, ln_g_g + d*E, ln_g_b + d*E, pxn);
        gemm_kernel<<<dim3(FF/64, S/64), 256>>>(pxn, W1 + (long)d*E*FF, b1 + (long)d*FF,
                                                nullptr, pffh, S, FF, E, 1);
        gemm_kernel<<<dim3(E/64, S/64), 256>>>(pffh, W2 + (long)d*FF*E, b2 + d*E, px2,
                                               px2, S, E, FF, 0);
    }

    sum_kernel<<<(S*E+255)/256, 256>>>();
    gemm_kernel<<<dim3(NVOCAB/64, S/64), 256>>>(psum, Wl, bl, nullptr, out,
                                                S, NVOCAB, E, 0);
}

// round 17
// speedup vs baseline: 1.7310x; 1.7310x over previous
#include <cuda_runtime.h>
#include <math.h>

#define S      4096
#define E      512
#define H      8
#define DH     64
#define NB     64
#define NH     4
#define FLAT   (NH*S)        // 16384
#define NCHUNK (NH*NB)       // 256
#define BH     H             // batch=1
#define FF     (4*E)         // 2048
#define NVOCAB 32000

// ---------------- scratch (device globals; no allocations allowed) ----------
__device__ float g_x1[S*E];
__device__ float g_x2[S*E];
__device__ float g_xn[S*E];
__device__ float g_qk[S*E];      // [s][h*64+d]
__device__ float g_v [S*E];
__device__ float g_attn[S*E];
__device__ float g_sum[S*E];
__device__ float g_ffh[S*FF];
__device__ int   g_buckets[BH*FLAT];
__device__ int   g_sidx[BH*FLAT];
__device__ float g_o[BH*NH*S*DH];
__device__ float g_logit[BH*NH*S];

// ================= flip-safe fast math =======================================
// exp/log flavor is measured flip-irrelevant (R13 cephes vs R15 fp64-cr moved
// rel_err by 2e-9 only). Use fp32 cephes — no fp64 pipe.
__device__ __forceinline__ float exp_f(float x) {
    float xx = fminf(fmaxf(x, -87.336548f), 88.723164f);
    float m = floorf(fmaf(xx, 1.44269504088896341f, 0.5f));
    float r = fmaf(m, -0.693359375f, xx);
    r = fmaf(m, 2.12194440e-4f, r);
    float r2 = __fmul_rn(r, r);
    float p = 1.9875691500e-4f;
    p = fmaf(p, r, 1.3981999507e-3f);
    p = fmaf(p, r, 8.3334519073e-3f);
    p = fmaf(p, r, 4.1665795894e-2f);
    p = fmaf(p, r, 1.6666665459e-1f);
    p = fmaf(p, r, 5.0000001201e-1f);
    float y = fmaf(p, r2, r);
    y = __fadd_rn(y, 1.0f);
    return ldexpf(y, (int)m);
}

__device__ __forceinline__ float log_f(float x) {
    int e;
    float f = frexpf(x, &e);                 // [0.5,1)
    if (f < 0.707106781186547524f) { f = __fadd_rn(f, f); e -= 1; }
    float z  = __fsub_rn(f, 1.0f);
    float zz = __fmul_rn(z, z);
    float p = 7.0376836292e-2f;
    p = fmaf(p, z, -1.1514610310e-1f);
    p = fmaf(p, z,  1.1676998740e-1f);
    p = fmaf(p, z, -1.2420140846e-1f);
    p = fmaf(p, z,  1.4249322787e-1f);
    p = fmaf(p, z, -1.6668057665e-1f);
    p = fmaf(p, z,  2.0000714765e-1f);
    p = fmaf(p, z, -2.4999993993e-1f);
    p = fmaf(p, z,  3.3333331174e-1f);
    float y = __fmul_rn(p, z);
    y = __fmul_rn(y, zz);
    float fe = (float)e;
    y = fmaf(fe, -2.12194440e-4f, y);
    y = fmaf(-0.5f, zz, y);
    float r = __fadd_rn(z, y);
    return fmaf(fe, 0.693359375f, r);
}

// lax.rsqrt on CPU: 1.0/sqrt(x), both correctly rounded. (flip-relevant: keep)
__device__ __forceinline__ float rsqrt_cr(float x) {
    return __fdiv_rn(1.0f, __fsqrt_rn(x));
}

// XLA EmitTanh f32 rational approximation (flip-relevant: keep exact).
__device__ __forceinline__ float tanh_xla(float x) {
    float ax = fabsf(x);
    if (ax < 0.0004f) return x;
    float xc = fminf(fmaxf(x, -7.90531110763549805f), 7.90531110763549805f);
    float x2 = __fmul_rn(xc, xc);
    float p = -2.76076847742355e-16f;
    p = fmaf(p, x2, 2.00018790482477e-13f);
    p = fmaf(p, x2, -8.60467152213735e-11f);
    p = fmaf(p, x2, 5.12229709037114e-08f);
    p = fmaf(p, x2, 1.48572235717979e-05f);
    p = fmaf(p, x2, 6.37261928875436e-04f);
    p = fmaf(p, x2, 4.89352455891786e-03f);
    float num = __fmul_rn(xc, p);
    float q = 1.19825839466702e-06f;
    q = fmaf(q, x2, 1.18534705686654e-04f);
    q = fmaf(q, x2, 2.26843463243900e-03f);
    q = fmaf(q, x2, 4.89352518554385e-03f);
    return __fdiv_rn(num, q);
}

// gelu with Python left-assoc rounding (flip-relevant: keep exact).
__device__ __forceinline__ float gelu_xla(float x) {
    float x2 = __fmul_rn(x, x);
    float x3 = __fmul_rn(x2, x);
    float inner = __fadd_rn(x, __fmul_rn(0.044715f, x3));
    float u = __fmul_rn(0.7978845608028654f, inner);
    float t = tanh_xla(u);
    float halfx = __fmul_rn(0.5f, x);
    return __fmul_rn(halfx, __fadd_rn(1.0f, t));
}

// ---------------- embed -----------------------------------------------------
__global__ void embed_kernel(const int* __restrict__ tokens,
                             const float* __restrict__ tok_emb,
                             const float* __restrict__ pos_emb) {
    int i = blockIdx.x * blockDim.x + threadIdx.x;
    if (i < S*E) {
        int s = i / E, e = i % E;
        float val = __fadd_rn(tok_emb[tokens[s]*E + e], pos_emb[i]);
        g_x1[i] = val; g_x2[i] = val;
    }
}

// ---------------- layernorm: one thread per row, STRICT SEQUENTIAL reduces ---
__global__ void ln_kernel(const float* __restrict__ x,
                          const float* __restrict__ g,
                          const float* __restrict__ b,
                          float* __restrict__ y) {
    int row = blockIdx.x * blockDim.x + threadIdx.x;
    if (row >= S) return;
    const float* xr = x + (long)row*E;
    float s = 0.f;
    for (int e = 0; e < E; e++) s = __fadd_rn(s, xr[e]);
    float mean = __fdiv_rn(s, 512.0f);
    float vs = 0.f;
    for (int e = 0; e < E; e++) {
        float d = __fsub_rn(xr[e], mean);
        vs = __fadd_rn(vs, __fmul_rn(d, d));
    }
    float var = __fdiv_rn(vs, 512.0f);
    float rstd = rsqrt_cr(__fadd_rn(var, 1e-3f));
    for (int e = 0; e < E; e++) {
        float d = __fsub_rn(xr[e], mean);
        y[(long)row*E + e] = __fadd_rn(__fmul_rn(__fmul_rn(d, rstd), g[e]), b[e]);
    }
}

// ---------------- 128x128 tiled GEMM, 8x8 microtile --------------------------
// Per-output accumulation chain: ascending-k sequential FMA — bitwise equal
// to Eigen gebp regardless of tiling. Epilogue order unchanged.
// Requires M%128==0, N%128==0, K%16==0 (all shapes here qualify).
__global__ void gemm_kernel(const float* __restrict__ A, const float* __restrict__ B,
                            const float* __restrict__ bias, const float* __restrict__ resid,
                            float* __restrict__ C, int M, int N, int K, int act) {
    __shared__ float As[16][132];
    __shared__ float Bs[16][128];
    int t  = threadIdx.x;            // 256
    int tx = t & 15, ty = t >> 4;    // 16 x 16 threads, each 8x8 outputs
    int n0 = blockIdx.x * 128, m0 = blockIdx.y * 128;
    float acc[8][8] = {};
    int a_mi = t >> 2;               // 0..63 (two rows: a_mi, a_mi+64)
    int a_ki = (t & 3) * 4;          // 0,4,8,12
    int b_ki = t >> 4;               // 0..15
    int b_ni = (t & 15) * 8;         // 0..120
    for (int k0 = 0; k0 < K; k0 += 16) {
        // A: 128 rows x 16 k; coalesced float4 along k, transposed store
        {
            float4 av = *(const float4*)&A[(long)(m0 + a_mi)*K + k0 + a_ki];
            As[a_ki+0][a_mi] = av.x; As[a_ki+1][a_mi] = av.y;
            As[a_ki+2][a_mi] = av.z; As[a_ki+3][a_mi] = av.w;
            float4 aw = *(const float4*)&A[(long)(m0 + a_mi + 64)*K + k0 + a_ki];
            As[a_ki+0][a_mi+64] = aw.x; As[a_ki+1][a_mi+64] = aw.y;
            As[a_ki+2][a_mi+64] = aw.z; As[a_ki+3][a_mi+64] = aw.w;
        }
        // B: 16 k x 128 n; coalesced float4 along n
        {
            const float* brow = &B[(long)(k0 + b_ki)*N + n0 + b_ni];
            *(float4*)&Bs[b_ki][b_ni]   = *(const float4*)&brow[0];
            *(float4*)&Bs[b_ki][b_ni+4] = *(const float4*)&brow[4];
        }
        __syncthreads();
        #pragma unroll
        for (int kk = 0; kk < 16; kk++) {
            float a[8], b[8];
            #pragma unroll
            for (int i = 0; i < 8; i++) a[i] = As[kk][ty*8+i];
            #pragma unroll
            for (int j = 0; j < 8; j++) b[j] = Bs[kk][tx*8+j];
            #pragma unroll
            for (int i = 0; i < 8; i++)
                #pragma unroll
                for (int j = 0; j < 8; j++)
                    acc[i][j] = fmaf(a[i], b[j], acc[i][j]);
        }
        __syncthreads();
    }
    #pragma unroll
    for (int i = 0; i < 8; i++) {
        int row = m0 + ty*8 + i;
        #pragma unroll
        for (int j = 0; j < 8; j++) {
            int col = n0 + tx*8 + j;
            float v = acc[i][j];
            if (bias)  v = __fadd_rn(v, bias[col]);
            if (act)   v = gelu_xla(v);
            if (resid) v = __fadd_rn(resid[(long)row*N + col], v);
            C[(long)row*N + col] = v;
        }
    }
}

// ---------------- LSH bucketing: sequential-k FMA dot, first-index argmax ----
__global__ void bucket_kernel(const float* __restrict__ rot) {
    int s = blockIdx.x, h = blockIdx.y, t = threadIdx.x;
    __shared__ float q[64];
    if (t < 64) q[t] = g_qk[s*E + h*DH + t];
    __syncthreads();
    int hash = t >> 5, r = t & 31;
    float v = 0.f;
    #pragma unroll 8
    for (int dd = 0; dd < 64; dd++)
        v = fmaf(q[dd], rot[dd*(NH*32) + hash*32 + r], v);
    float val; int idx;
    if (v >= -v) { val = v;  idx = r; }
    else         { val = -v; idx = r + 32; }
    unsigned mask = 0xffffffffu;
    for (int off = 16; off; off >>= 1) {
        float ov = __shfl_down_sync(mask, val, off);
        int   oi = __shfl_down_sync(mask, idx, off);
        if (ov > val || (ov == val && oi < idx)) { val = ov; idx = oi; }
    }
    if (r == 0) g_buckets[h*FLAT + hash*S + s] = idx + hash*NB;
}

// ---------------- stable counting sort (per bh; 256 bins) --------------------
__global__ void sort_kernel() {
    int bh = blockIdx.x, t = threadIdx.x;    // 256 threads
    const int* bk = g_buckets + bh*FLAT;
    int cnt = 0;
    #pragma unroll 8
    for (int i = 0; i < FLAT; i++) cnt += (bk[i] == t);
    __shared__ int c[256];
    c[t] = cnt; __syncthreads();
    int off = 0;
    for (int j = 0; j < t; j++) off += c[j];
    int* dst = g_sidx + bh*FLAT;
    #pragma unroll 4
    for (int i = 0; i < FLAT; i++)
        if (bk[i] == t) dst[off++] = i;
}

// ---------------- chunked attention ------------------------------------------
// Batched small einsums: UNFUSED mul+add (flip-relevant; keep). exp/log fp32.
#define SK_LD   65
#define DOTS_LD 129
#define ATTN_SMEM_BYTES ((128*SK_LD*3 + 64*DOTS_LD + 128)*4 + 256*4)

__global__ void attn_kernel() {
    extern __shared__ float sh[];
    float* sk    = sh;                       // [128][65] raw qk rows
    float* bvs   = sk  + 128*SK_LD;          // [128][65] v rows
    float* bkn   = bvs + 128*SK_LD;          // [128][65] normalized keys (f32)
    float* dots  = bkn + 128*SK_LD;          // [64][129]
    float* rnorm = dots + 64*DOTS_LD;        // [128]
    int*   spos  = (int*)(rnorm + 128);      // [128]
    int*   shash = spos + 128;               // [128]

    int c  = blockIdx.x;
    int bh = blockIdx.y;
    int t  = threadIdx.x;
    int cp = (c + NCHUNK - 1) % NCHUNK;

    if (t < 128) {
        int kr = t;
        int js = (kr < 64) ? (c*64 + kr) : (cp*64 + (kr - 64));
        int i  = g_sidx[bh*FLAT + js];
        spos[kr]  = i & (S-1);
        shash[kr] = i >> 12;
    }
    __syncthreads();

    for (int idx = t; idx < 128*64; idx += 256) {
        int kr = idx >> 6, dd = idx & 63;
        int p = spos[kr];
        sk [kr*SK_LD + dd] = g_qk[p*E + bh*DH + dd];
        bvs[kr*SK_LD + dd] = g_v [p*E + bh*DH + dd];
    }
    __syncthreads();

    // sum of squares: strict sequential, unfused mul/add
    if (t < 128) {
        float ss = 0.f;
        for (int dd = 0; dd < 64; dd++) {
            float v = sk[t*SK_LD+dd];
            ss = __fadd_rn(ss, __fmul_rn(v, v));
        }
        rnorm[t] = rsqrt_cr(__fadd_rn(ss, 1e-12f));
    }
    __syncthreads();

    for (int idx = t; idx < 128*64; idx += 256) {
        int kr = idx >> 6, dd = idx & 63;
        bkn[kr*SK_LD + dd] = __fmul_rn(sk[kr*SK_LD + dd], rnorm[kr]);
    }
    __syncthreads();

    // dots = (bq . bkn) [UNFUSED mul+add, sequential] * 0.125, self-pos mask
    for (int task = t; task < 64*32; task += 256) {
        int r = task >> 5, k0 = (task & 31) * 4;
        float a0=0.f, a1=0.f, a2=0.f, a3=0.f;
        #pragma unroll 8
        for (int dd = 0; dd < 64; dd++) {
            float q = sk[r*SK_LD + dd];
            a0 = __fadd_rn(a0, __fmul_rn(q, bkn[(k0+0)*SK_LD+dd]));
            a1 = __fadd_rn(a1, __fmul_rn(q, bkn[(k0+1)*SK_LD+dd]));
            a2 = __fadd_rn(a2, __fmul_rn(q, bkn[(k0+2)*SK_LD+dd]));
            a3 = __fadd_rn(a3, __fmul_rn(q, bkn[(k0+3)*SK_LD+dd]));
        }
        int pr = spos[r];
        dots[r*DOTS_LD+k0+0] = (pr == spos[k0+0]) ? -5e4f : __fmul_rn(a0, 0.125f);
        dots[r*DOTS_LD+k0+1] = (pr == spos[k0+1]) ? -5e4f : __fmul_rn(a1, 0.125f);
        dots[r*DOTS_LD+k0+2] = (pr == spos[k0+2]) ? -5e4f : __fmul_rn(a2, 0.125f);
        dots[r*DOTS_LD+k0+3] = (pr == spos[k0+3]) ? -5e4f : __fmul_rn(a3, 0.125f);
    }
    __syncthreads();

    // logsumexp (strict sequential sum, fp32 exp/log)
    if (t < 64) {
        float m = -1e30f;
        for (int k = 0; k < 128; k++) m = fmaxf(m, dots[t*DOTS_LD+k]);
        float ssum = 0.f;
        for (int k = 0; k < 128; k++)
            ssum = __fadd_rn(ssum, exp_f(__fsub_rn(dots[t*DOTS_LD+k], m)));
        float lse = __fadd_rn(log_f(ssum), m);
        g_logit[(bh*NH + shash[t])*S + spos[t]] = lse;
        for (int k = 0; k < 128; k++)
            dots[t*DOTS_LD+k] = exp_f(__fsub_rn(dots[t*DOTS_LD+k], lse));
    }
    __syncthreads();

    // bo = probs @ bv (UNFUSED mul+add, sequential over k), scatter-unsort
    for (int task = t; task < 64*16; task += 256) {
        int r = task >> 4, d0 = (task & 15) * 4;
        float o0=0.f, o1=0.f, o2=0.f, o3=0.f;
        for (int k = 0; k < 128; k++) {
            float p = dots[r*DOTS_LD + k];
            o0 = __fadd_rn(o0, __fmul_rn(p, bvs[k*SK_LD + d0+0]));
            o1 = __fadd_rn(o1, __fmul_rn(p, bvs[k*SK_LD + d0+1]));
            o2 = __fadd_rn(o2, __fmul_rn(p, bvs[k*SK_LD + d0+2]));
            o3 = __fadd_rn(o3, __fmul_rn(p, bvs[k*SK_LD + d0+3]));
        }
        long base = ((long)(bh*NH + shash[r])*S + spos[r])*DH + d0;
        g_o[base+0] = o0; g_o[base+1] = o1; g_o[base+2] = o2; g_o[base+3] = o3;
    }
}

// ---------------- combine hash rounds (strict sequential, fp32 exp/log) ------
__global__ void combine_kernel() {
    int gid = blockIdx.x * blockDim.x + threadIdx.x;
    if (gid >= BH*S*DH) return;
    int dd  = gid & 63;
    int pos = (gid >> 6) & (S-1);
    int bh  = gid >> 18;
    float l0 = g_logit[(bh*NH+0)*S+pos];
    float l1 = g_logit[(bh*NH+1)*S+pos];
    float l2 = g_logit[(bh*NH+2)*S+pos];
    float l3 = g_logit[(bh*NH+3)*S+pos];
    float m  = fmaxf(fmaxf(fmaxf(l0,l1),l2),l3);
    float s4 = 0.f;
    s4 = __fadd_rn(s4, exp_f(__fsub_rn(l0,m)));
    s4 = __fadd_rn(s4, exp_f(__fsub_rn(l1,m)));
    s4 = __fadd_rn(s4, exp_f(__fsub_rn(l2,m)));
    s4 = __fadd_rn(s4, exp_f(__fsub_rn(l3,m)));
    float lse4 = __fadd_rn(log_f(s4), m);
    float w0 = exp_f(__fsub_rn(l0,lse4)), w1 = exp_f(__fsub_rn(l1,lse4));
    float w2 = exp_f(__fsub_rn(l2,lse4)), w3 = exp_f(__fsub_rn(l3,lse4));
    float acc = 0.f;
    acc = __fadd_rn(acc, __fmul_rn(g_o[((long)(bh*NH+0)*S+pos)*DH+dd], w0));
    acc = __fadd_rn(acc, __fmul_rn(g_o[((long)(bh*NH+1)*S+pos)*DH+dd], w1));
    acc = __fadd_rn(acc, __fmul_rn(g_o[((long)(bh*NH+2)*S+pos)*DH+dd], w2));
    acc = __fadd_rn(acc, __fmul_rn(g_o[((long)(bh*NH+3)*S+pos)*DH+dd], w3));
    g_attn[pos*E + bh*DH + dd] = acc;
}

// ---------------- x1 + x2 -----------------------------------------------------
__global__ void sum_kernel() {
    int i = blockIdx.x * blockDim.x + threadIdx.x;
    if (i < S*E) g_sum[i] = __fadd_rn(g_x1[i], g_x2[i]);
}

// ---------------- launch -------------------------------------------------------
extern "C" void kernel_launch(void* const* d_in, const int* in_sizes, int n_in,
                              void* d_out, int out_size) {
    const int*   tokens  = (const int*)  d_in[0];
    const float* tok_emb = (const float*)d_in[1];
    const float* pos_emb = (const float*)d_in[2];
    const float* ln_f_g  = (const float*)d_in[3];
    const float* ln_f_b  = (const float*)d_in[4];
    const float* Wqk     = (const float*)d_in[5];
    const float* Wv      = (const float*)d_in[6];
    const float* Wo      = (const float*)d_in[7];
    const float* bo      = (const float*)d_in[8];
    const float* ln_g_g  = (const float*)d_in[9];
    const float* ln_g_b  = (const float*)d_in[10];
    const float* W1      = (const float*)d_in[11];
    const float* b1      = (const float*)d_in[12];
    const float* W2      = (const float*)d_in[13];
    const float* b2      = (const float*)d_in[14];
    const float* rot     = (const float*)d_in[15];
    const float* Wl      = (const float*)d_in[16];
    const float* bl      = (const float*)d_in[17];
    float* out = (float*)d_out;

    cudaFuncSetAttribute(attn_kernel, cudaFuncAttributeMaxDynamicSharedMemorySize,
                         ATTN_SMEM_BYTES);

    float *px1, *px2, *pxn, *pqk, *pv, *pattn, *pffh, *psum;
    cudaGetSymbolAddress((void**)&px1,  g_x1);
    cudaGetSymbolAddress((void**)&px2,  g_x2);
    cudaGetSymbolAddress((void**)&pxn,  g_xn);
    cudaGetSymbolAddress((void**)&pqk,  g_qk);
    cudaGetSymbolAddress((void**)&pv,   g_v);
    cudaGetSymbolAddress((void**)&pattn,g_attn);
    cudaGetSymbolAddress((void**)&pffh, g_ffh);
    cudaGetSymbolAddress((void**)&psum, g_sum);

    embed_kernel<<<(S*E+255)/256, 256>>>(tokens, tok_emb, pos_emb);

    for (int d = 0; d < 4; d++) {
        // attention branch: y1 = x1 + attn(LN(x2))
        ln_kernel<<<S/128, 128>>>(px2, ln_f_g + d*E, ln_f_b + d*E, pxn);
        gemm_kernel<<<dim3(E/128, S/128), 256>>>(pxn, Wqk + (long)d*E*E, nullptr, nullptr,
                                                 pqk, S, E, E, 0);
        gemm_kernel<<<dim3(E/128, S/128), 256>>>(pxn, Wv  + (long)d*E*E, nullptr, nullptr,
                                                 pv,  S, E, E, 0);
        bucket_kernel<<<dim3(S, H), 128>>>(rot + (long)d*DH*NH*32);
        sort_kernel<<<BH, 256>>>();
        attn_kernel<<<dim3(NCHUNK, BH), 256, ATTN_SMEM_BYTES>>>();
        combine_kernel<<<(BH*S*DH + 255)/256, 256>>>();
        gemm_kernel<<<dim3(E/128, S/128), 256>>>(pattn, Wo + (long)d*E*E, bo + d*E, px1,
                                                 px1, S, E, E, 0);
        // ffn branch: y2 = x2 + FFN(LN(y1))
        ln_kernel<<<S/128, 128>>>(px1, ln_g_g + d*E, ln_g_b + d*E, pxn);
        gemm_kernel<<<dim3(FF/128, S/128), 256>>>(pxn, W1 + (long)d*E*FF, b1 + (long)d*FF,
                                                  nullptr, pffh, S, FF, E, 1);
        gemm_kernel<<<dim3(E/128, S/128), 256>>>(pffh, W2 + (long)d*FF*E, b2 + d*E, px2,
                                                 px2, S, E, FF, 0);
    }

    sum_kernel<<<(S*E+255)/256, 256>>>();
    gemm_kernel<<<dim3(NVOCAB/128, S/128), 256>>>(psum, Wl, bl, nullptr, out,
                                                  S, NVOCAB, E, 0);
}